// round 16
// baseline (speedup 1.0000x reference)
#include <cuda_runtime.h>
#include <math.h>

#define LQ 1600
#define CD 256
#define NHD 8
#define HD 32
#define DFF 1024
#define GH 40
#define GW 40
#define EPSV 1e-5f
#define QSCALE 0.17677669529663687f  // 1/sqrt(32)
#define NSPLIT 3

// weight-split offsets in the flat hi/lo pool
#define OFF_WQ   0
#define OFF_WK   65536
#define OFF_WV   131072
#define OFF_WO   196608
#define OFF_WQV  262144
#define OFF_WID  393216
#define OFF_WCAT 460800
#define OFF_W1   591872
#define OFF_W2   854016
#define WTOT     1116160
#define SPLIT_TOT (WTOT + LQ*CD)

// ---------------- tf32 mma helpers ----------------
__device__ __forceinline__ unsigned tf32r(float x) {
  unsigned u; asm("cvt.rna.tf32.f32 %0, %1;" : "=r"(u) : "f"(x)); return u;
}
__device__ __forceinline__ void mma_tf32(float* d, const unsigned* a, unsigned b0, unsigned b1) {
  asm("mma.sync.aligned.m16n8k8.row.col.f32.tf32.tf32.f32 "
      "{%0,%1,%2,%3}, {%4,%5,%6,%7}, {%8,%9}, {%0,%1,%2,%3};"
      : "+f"(d[0]), "+f"(d[1]), "+f"(d[2]), "+f"(d[3])
      : "r"(a[0]), "r"(a[1]), "r"(a[2]), "r"(a[3]), "r"(b0), "r"(b1));
}

// ---------------- scratch (device globals; no allocation) ----------------
static __device__ float g_thi[LQ*CD];
static __device__ float g_tlo[LQ*CD];
static __device__ float g_qkhi[LQ*CD];
static __device__ float g_qklo[LQ*CD];
static __device__ float g_q[LQ*CD];
static __device__ float g_khi[LQ*CD];
static __device__ float g_klo[LQ*CD];
static __device__ float g_vhi[LQ*CD];
static __device__ float g_vlo[LQ*CD];
static __device__ float g_tgt[LQ*CD];
static __device__ float g_qv[LQ*2*CD];
static __device__ float g_idkv[LQ*264];
static __device__ float g_gK[LQ*CD];
static __device__ float g_gV[LQ*CD];
static __device__ float g_acathi[LQ*512];
static __device__ float g_acatlo[LQ*512];
static __device__ float g_x[LQ*DFF];
static __device__ float g_x2[LQ*DFF];
static __device__ float g_xhi[LQ*DFF];
static __device__ float g_xlo[LQ*DFF];
static __device__ float g_stats[64];
static __device__ float g_bcat[256];
static __device__ float g_whi[WTOT];
static __device__ float g_wlo[WTOT];
static __device__ float g_idehi[LQ*CD];
static __device__ float g_idelo[LQ*CD];
static __device__ float g_opart[NSPLIT*LQ*CD];
static __device__ float2 g_ml[NSPLIT*LQ*NHD];

// ---------------- split all weights + id_emb into hi/lo ----------------
__global__ __launch_bounds__(256) void wsplit_all(
    const float* __restrict__ wq, const float* __restrict__ wk,
    const float* __restrict__ wv, const float* __restrict__ wo,
    const float* __restrict__ wqv, const float* __restrict__ wid,
    const float* __restrict__ lt, const float* __restrict__ st,
    const float* __restrict__ w1, const float* __restrict__ w2,
    const float* __restrict__ ide,
    float* __restrict__ whi, float* __restrict__ wlo,
    float* __restrict__ idehi, float* __restrict__ idelo) {
  int idx = blockIdx.x * 256 + threadIdx.x;
  if (idx >= SPLIT_TOT) return;
  if (idx >= WTOT) {
    int j = idx - WTOT;
    float v = ide[j];
    float hi = __uint_as_float(tf32r(v));
    idehi[j] = hi;
    idelo[j] = __uint_as_float(tf32r(v - hi));
    return;
  }
  float v;
  if      (idx < OFF_WK)   v = wq[idx];
  else if (idx < OFF_WV)   v = wk[idx - OFF_WK];
  else if (idx < OFF_WO)   v = wv[idx - OFF_WV];
  else if (idx < OFF_WQV)  v = wo[idx - OFF_WO];
  else if (idx < OFF_WID)  v = wqv[idx - OFF_WQV];
  else if (idx < OFF_WCAT) v = wid[idx - OFF_WID];
  else if (idx < OFF_W1) {
    int j = idx - OFF_WCAT; int nrow = j >> 9; int kc = j & 511;
    v = (kc < 256) ? lt[nrow*256 + kc] : st[nrow*256 + kc - 256];
  }
  else if (idx < OFF_W2)   v = w1[idx - OFF_W1];
  else                     v = w2[idx - OFF_W2];
  float hi = __uint_as_float(tf32r(v));
  whi[idx] = hi;
  wlo[idx] = __uint_as_float(tf32r(v - hi));
}

__global__ __launch_bounds__(256) void pack_b(
    const float* __restrict__ ltb, const float* __restrict__ stb, float* __restrict__ bcat) {
  int i = threadIdx.x;
  bcat[i] = ltb[i] + stb[i];
}

// ---------------- LayerNorm: emits hi/lo (+ optional pos-add hi/lo) --------
__global__ __launch_bounds__(256) void ln_kernel(
    const float* __restrict__ x, const float* __restrict__ g, const float* __restrict__ b,
    float* __restrict__ yhi, float* __restrict__ ylo,
    const float* __restrict__ pos, float* __restrict__ qkhi, float* __restrict__ qklo) {
  int l = blockIdx.x;
  int c = threadIdx.x;
  float v = x[(size_t)l*CD + c];
  float s = v, s2 = v*v;
  #pragma unroll
  for (int o = 16; o; o >>= 1) {
    s  += __shfl_xor_sync(0xffffffffu, s,  o);
    s2 += __shfl_xor_sync(0xffffffffu, s2, o);
  }
  __shared__ float sh[8], sh2[8], smv[2];
  int w = c >> 5, lane = c & 31;
  if (lane == 0) { sh[w] = s; sh2[w] = s2; }
  __syncthreads();
  if (c == 0) {
    float a = 0.f, a2 = 0.f;
    #pragma unroll
    for (int i = 0; i < 8; i++) { a += sh[i]; a2 += sh2[i]; }
    float mean = a * (1.0f/CD);
    float var  = a2 * (1.0f/CD) - mean*mean;
    smv[0] = mean; smv[1] = rsqrtf(var + EPSV);
  }
  __syncthreads();
  float out = (v - smv[0]) * smv[1] * g[c] + b[c];
  float hi = __uint_as_float(tf32r(out));
  yhi[(size_t)l*CD + c] = hi;
  ylo[(size_t)l*CD + c] = __uint_as_float(tf32r(out - hi));
  if (qkhi) {
    float o2 = out + pos[(size_t)l*CD + c];
    float h2 = __uint_as_float(tf32r(o2));
    qkhi[(size_t)l*CD + c] = h2;
    qklo[(size_t)l*CD + c] = __uint_as_float(tf32r(o2 - h2));
  }
}

// ---------------- GEMM core: tf32 3x mma, pre-split operands ---------------
// C[M,N]=A[M,K]@B[N,K]^T + bias (+res). 64x64 tile, 256 threads = 2 K-halves
// x 4 warps. Producer is pure load->store (no cvt). Optional hi/lo output.
__device__ __forceinline__ void gemm_body(
    const float* __restrict__ Ahi, const float* __restrict__ Alo,
    const float* __restrict__ Bhi, const float* __restrict__ Blo,
    const float* __restrict__ bias, const float* __restrict__ res,
    float* __restrict__ Cout, float* __restrict__ Chi, float* __restrict__ Clo,
    int M, int N, int K, int bm, int bn) {
  __shared__ float pool[2][4][64*20];   // [half][Ah,Al,Bh,Bl][64 rows x 20]
  const int tid = threadIdx.x;
  const int h = tid >> 7;
  const int htid = tid & 127;
  const int w = htid >> 5, lane = htid & 31;
  const int g = lane >> 2, t = lane & 3;
  const int rw = w * 16;
  const int lr = htid >> 1;
  const int c8 = (htid & 1) << 3;
  const int Kh = K >> 1;
  const int nh = K >> 5;
  const bool bok = (bn + lr) < N;

  float acc[8][4];
  #pragma unroll
  for (int n = 0; n < 8; n++) { acc[n][0]=0.f; acc[n][1]=0.f; acc[n][2]=0.f; acc[n][3]=0.f; }

  float4 pah[2], pal[2], pbh[2], pbl[2];
  {
    size_t ab = (size_t)(bm+lr)*K + h*Kh + c8;
    size_t bb = (size_t)(bn+lr)*K + h*Kh + c8;
    pah[0] = *(const float4*)(Ahi+ab); pah[1] = *(const float4*)(Ahi+ab+4);
    pal[0] = *(const float4*)(Alo+ab); pal[1] = *(const float4*)(Alo+ab+4);
    if (bok) {
      pbh[0] = *(const float4*)(Bhi+bb); pbh[1] = *(const float4*)(Bhi+bb+4);
      pbl[0] = *(const float4*)(Blo+bb); pbl[1] = *(const float4*)(Blo+bb+4);
    } else {
      pbh[0]=pbh[1]=pbl[0]=pbl[1]=make_float4(0.f,0.f,0.f,0.f);
    }
  }

  for (int c = 0; c < nh; c++) {
    __syncthreads();
    {
      int off = lr*20 + c8;
      *(float4*)&pool[h][0][off]   = pah[0]; *(float4*)&pool[h][0][off+4] = pah[1];
      *(float4*)&pool[h][1][off]   = pal[0]; *(float4*)&pool[h][1][off+4] = pal[1];
      *(float4*)&pool[h][2][off]   = pbh[0]; *(float4*)&pool[h][2][off+4] = pbh[1];
      *(float4*)&pool[h][3][off]   = pbl[0]; *(float4*)&pool[h][3][off+4] = pbl[1];
    }
    __syncthreads();
    if (c + 1 < nh) {
      size_t ab = (size_t)(bm+lr)*K + h*Kh + (c+1)*16 + c8;
      size_t bb = (size_t)(bn+lr)*K + h*Kh + (c+1)*16 + c8;
      pah[0] = *(const float4*)(Ahi+ab); pah[1] = *(const float4*)(Ahi+ab+4);
      pal[0] = *(const float4*)(Alo+ab); pal[1] = *(const float4*)(Alo+ab+4);
      if (bok) {
        pbh[0] = *(const float4*)(Bhi+bb); pbh[1] = *(const float4*)(Bhi+bb+4);
        pbl[0] = *(const float4*)(Blo+bb); pbl[1] = *(const float4*)(Blo+bb+4);
      } else {
        pbh[0]=pbh[1]=pbl[0]=pbl[1]=make_float4(0.f,0.f,0.f,0.f);
      }
    }
    #pragma unroll
    for (int ks = 0; ks < 2; ks++) {
      const int acol = ks*8;
      unsigned qh[4], ql[4];
      qh[0] = __float_as_uint(pool[h][0][(rw+g  )*20 + acol + t  ]);
      qh[1] = __float_as_uint(pool[h][0][(rw+g+8)*20 + acol + t  ]);
      qh[2] = __float_as_uint(pool[h][0][(rw+g  )*20 + acol + t+4]);
      qh[3] = __float_as_uint(pool[h][0][(rw+g+8)*20 + acol + t+4]);
      ql[0] = __float_as_uint(pool[h][1][(rw+g  )*20 + acol + t  ]);
      ql[1] = __float_as_uint(pool[h][1][(rw+g+8)*20 + acol + t  ]);
      ql[2] = __float_as_uint(pool[h][1][(rw+g  )*20 + acol + t+4]);
      ql[3] = __float_as_uint(pool[h][1][(rw+g+8)*20 + acol + t+4]);
      #pragma unroll
      for (int n = 0; n < 8; n++) {
        unsigned bh0 = __float_as_uint(pool[h][2][(n*8+g)*20 + acol + t  ]);
        unsigned bh1 = __float_as_uint(pool[h][2][(n*8+g)*20 + acol + t+4]);
        unsigned bl0 = __float_as_uint(pool[h][3][(n*8+g)*20 + acol + t  ]);
        unsigned bl1 = __float_as_uint(pool[h][3][(n*8+g)*20 + acol + t+4]);
        mma_tf32(acc[n], qh, bh0, bh1);
        mma_tf32(acc[n], qh, bl0, bl1);
        mma_tf32(acc[n], ql, bh0, bh1);
      }
    }
  }

  float (*red)[68] = (float(*)[68])&pool[0][0][0];
  __syncthreads();
  if (h == 1) {
    #pragma unroll
    for (int n = 0; n < 8; n++) {
      *(float2*)&red[rw+g  ][n*8+2*t] = make_float2(acc[n][0], acc[n][1]);
      *(float2*)&red[rw+g+8][n*8+2*t] = make_float2(acc[n][2], acc[n][3]);
    }
  }
  __syncthreads();
  if (h == 0) {
    #pragma unroll
    for (int n = 0; n < 8; n++) {
      int cn = bn + n*8 + 2*t;
      float2 r0 = *(const float2*)&red[rw+g  ][n*8+2*t];
      float2 r1 = *(const float2*)&red[rw+g+8][n*8+2*t];
      int m0 = bm + rw + g, m1 = bm + rw + g + 8;
      float vv[2][2] = {{acc[n][0]+r0.x, acc[n][1]+r0.y},
                        {acc[n][2]+r1.x, acc[n][3]+r1.y}};
      #pragma unroll
      for (int j = 0; j < 2; j++) {
        int cnn = cn + j;
        if (cnn >= N) continue;
        float v0 = vv[0][j] + bias[cnn];
        float v1 = vv[1][j] + bias[cnn];
        if (res) { v0 += res[(size_t)m0*N + cnn]; v1 += res[(size_t)m1*N + cnn]; }
        if (Cout) {
          Cout[(size_t)m0*N + cnn] = v0;
          Cout[(size_t)m1*N + cnn] = v1;
        }
        if (Chi) {
          float h0 = __uint_as_float(tf32r(v0));
          float h1 = __uint_as_float(tf32r(v1));
          Chi[(size_t)m0*N + cnn] = h0;
          Chi[(size_t)m1*N + cnn] = h1;
          Clo[(size_t)m0*N + cnn] = __uint_as_float(tf32r(v0 - h0));
          Clo[(size_t)m1*N + cnn] = __uint_as_float(tf32r(v1 - h1));
        }
      }
    }
  }
}

__global__ __launch_bounds__(256) void gemm_nt(
    const float* __restrict__ Ahi, const float* __restrict__ Alo,
    const float* __restrict__ Bhi, const float* __restrict__ Blo,
    const float* __restrict__ bias, const float* __restrict__ res,
    float* __restrict__ Cout, float* __restrict__ Chi, float* __restrict__ Clo,
    int M, int N, int K) {
  gemm_body(Ahi, Alo, Bhi, Blo, bias, res, Cout, Chi, Clo, M, N, K,
            blockIdx.y*64, blockIdx.x*64);
}

// fused q/k/v projections; k and v emit hi/lo for the attention kernel
__global__ __launch_bounds__(256) void gemm_qkv(
    const float* __restrict__ qkhi, const float* __restrict__ qklo,
    const float* __restrict__ thi, const float* __restrict__ tlo,
    const float* __restrict__ whi, const float* __restrict__ wlo,
    const float* __restrict__ bq, const float* __restrict__ bk, const float* __restrict__ bv,
    float* __restrict__ q,
    float* __restrict__ khi, float* __restrict__ klo,
    float* __restrict__ vhi, float* __restrict__ vlo) {
  int z = blockIdx.z;
  const float* Ahi = (z == 2) ? thi : qkhi;
  const float* Alo = (z == 2) ? tlo : qklo;
  const float* Bhi = whi + ((z == 0) ? OFF_WQ : (z == 1 ? OFF_WK : OFF_WV));
  const float* Blo = wlo + ((z == 0) ? OFF_WQ : (z == 1 ? OFF_WK : OFF_WV));
  const float* bias = (z == 0) ? bq : (z == 1 ? bk : bv);
  float* Cout = (z == 0) ? q : nullptr;
  float* Chi  = (z == 0) ? nullptr : (z == 1 ? khi : vhi);
  float* Clo  = (z == 0) ? nullptr : (z == 1 ? klo : vlo);
  gemm_body(Ahi, Alo, Bhi, Blo, bias, nullptr, Cout, Chi, Clo,
            LQ, CD, CD, blockIdx.y*64, blockIdx.x*64);
}

// ---------------- Fused full attention: tf32 3x mma, pre-split K/V ---------
// grid (25 q-tiles, 8 heads, 3 kv-splits), 128 threads (4 warps x 16 q-rows).
__global__ __launch_bounds__(128, 4) void attn_kernel(
    const float* __restrict__ Q,
    const float* __restrict__ Khi, const float* __restrict__ Klo,
    const float* __restrict__ Vhi, const float* __restrict__ Vlo,
    float* __restrict__ Opart, float2* __restrict__ ml) {
  __shared__ float Vs_hi[64][40];
  __shared__ float Vs_lo[64][40];
  __shared__ float uKP[4608];   // Ks_hi [64][36] | Ks_lo +2304 ; reused as Ps[64][68]
  #define KS_HI(kk,dd) uKP[(kk)*36 + (dd)]
  #define KS_LO(kk,dd) uKP[2304 + (kk)*36 + (dd)]
  #define PS(rr,cc)    uKP[(rr)*68 + (cc)]

  const int h = blockIdx.y;
  const int z = blockIdx.z;
  const int q0 = blockIdx.x * 64;
  const int kt0 = (z == 0) ? 0 : 9 + (z - 1) * 8;
  const int kt1 = (z == 0) ? 9 : kt0 + 8;
  const int tid = threadIdx.x;
  const int w = tid >> 5, lane = tid & 31;
  const int g = lane >> 2, t = lane & 3;
  const int qb = q0 + w*16;

  // --- Q fragments (hi/lo tf32), loaded once ---
  unsigned qhi[4][4], qlo[4][4];
  #pragma unroll
  for (int s = 0; s < 4; s++) {
    const int k0 = s*8;
    float f[4];
    f[0] = Q[(size_t)(qb+g  )*CD + h*HD + k0 + t    ] * QSCALE;
    f[1] = Q[(size_t)(qb+g+8)*CD + h*HD + k0 + t    ] * QSCALE;
    f[2] = Q[(size_t)(qb+g  )*CD + h*HD + k0 + t + 4] * QSCALE;
    f[3] = Q[(size_t)(qb+g+8)*CD + h*HD + k0 + t + 4] * QSCALE;
    #pragma unroll
    for (int i = 0; i < 4; i++) {
      qhi[s][i] = tf32r(f[i]);
      qlo[s][i] = tf32r(f[i] - __uint_as_float(qhi[s][i]));
    }
  }

  float m_i[2] = {-1e30f, -1e30f};
  float l_i[2] = {0.f, 0.f};
  float oacc[4][4] = {};

  for (int kt = kt0; kt < kt1; kt++) {
    const int kb = kt * 64;
    __syncthreads();   // prior tile fully consumed
    // --- producer: pure load -> smem, no conversion ---
    #pragma unroll
    for (int it = 0; it < 4; it++) {
      int idx = tid + it*128;
      int r = idx >> 3, d4 = (idx & 7) << 2;
      size_t gofs = (size_t)(kb + r)*CD + h*HD + d4;
      *(float4*)&KS_HI(r, d4) = *(const float4*)(Khi + gofs);
      *(float4*)&KS_LO(r, d4) = *(const float4*)(Klo + gofs);
      *(float4*)&Vs_hi[r][d4] = *(const float4*)(Vhi + gofs);
      *(float4*)&Vs_lo[r][d4] = *(const float4*)(Vlo + gofs);
    }
    __syncthreads();

    // --- QK^T: S[16 x 64] per warp via 3xTF32 mma ---
    float sacc[8][4];
    #pragma unroll
    for (int n = 0; n < 8; n++)
      #pragma unroll
      for (int i = 0; i < 4; i++) sacc[n][i] = 0.f;
    #pragma unroll
    for (int n = 0; n < 8; n++) {
      #pragma unroll
      for (int s = 0; s < 4; s++) {
        unsigned bh0 = __float_as_uint(KS_HI(n*8+g, s*8+t));
        unsigned bh1 = __float_as_uint(KS_HI(n*8+g, s*8+t+4));
        unsigned bl0 = __float_as_uint(KS_LO(n*8+g, s*8+t));
        unsigned bl1 = __float_as_uint(KS_LO(n*8+g, s*8+t+4));
        mma_tf32(sacc[n], qhi[s], bh0, bh1);
        mma_tf32(sacc[n], qhi[s], bl0, bl1);
        mma_tf32(sacc[n], qlo[s], bh0, bh1);
      }
    }
    __syncthreads();   // all warps done reading Ks before Ps overwrites uKP

    // --- online softmax ---
    #pragma unroll
    for (int ri = 0; ri < 2; ri++) {
      float rm = -1e30f;
      #pragma unroll
      for (int n = 0; n < 8; n++)
        rm = fmaxf(rm, fmaxf(sacc[n][2*ri], sacc[n][2*ri+1]));
      rm = fmaxf(rm, __shfl_xor_sync(0xffffffffu, rm, 1));
      rm = fmaxf(rm, __shfl_xor_sync(0xffffffffu, rm, 2));
      float mnew = fmaxf(m_i[ri], rm);
      float alpha = __expf(m_i[ri] - mnew);
      float rs = 0.f;
      int prow = w*16 + g + ri*8;
      #pragma unroll
      for (int n = 0; n < 8; n++) {
        float p0 = __expf(sacc[n][2*ri]   - mnew);
        float p1 = __expf(sacc[n][2*ri+1] - mnew);
        *(float2*)&PS(prow, n*8 + 2*t) = make_float2(p0, p1);
        rs += p0 + p1;
      }
      rs += __shfl_xor_sync(0xffffffffu, rs, 1);
      rs += __shfl_xor_sync(0xffffffffu, rs, 2);
      l_i[ri] = l_i[ri]*alpha + rs;
      m_i[ri] = mnew;
      #pragma unroll
      for (int n = 0; n < 4; n++) { oacc[n][2*ri] *= alpha; oacc[n][2*ri+1] *= alpha; }
    }
    __syncwarp();

    // --- P @ V via 3xTF32 mma ---
    #pragma unroll
    for (int kk = 0; kk < 8; kk++) {
      float pf[4];
      pf[0] = PS(w*16 + g,     kk*8 + t);
      pf[1] = PS(w*16 + g + 8, kk*8 + t);
      pf[2] = PS(w*16 + g,     kk*8 + t + 4);
      pf[3] = PS(w*16 + g + 8, kk*8 + t + 4);
      unsigned ahi[4], alo[4];
      #pragma unroll
      for (int i = 0; i < 4; i++) {
        ahi[i] = tf32r(pf[i]);
        alo[i] = tf32r(pf[i] - __uint_as_float(ahi[i]));
      }
      #pragma unroll
      for (int n = 0; n < 4; n++) {
        unsigned bh0 = __float_as_uint(Vs_hi[kk*8+t  ][n*8+g]);
        unsigned bh1 = __float_as_uint(Vs_hi[kk*8+t+4][n*8+g]);
        unsigned bl0 = __float_as_uint(Vs_lo[kk*8+t  ][n*8+g]);
        unsigned bl1 = __float_as_uint(Vs_lo[kk*8+t+4][n*8+g]);
        mma_tf32(oacc[n], ahi, bh0, bh1);
        mma_tf32(oacc[n], ahi, bl0, bl1);
        mma_tf32(oacc[n], alo, bh0, bh1);
      }
    }
  }

  // --- epilogue: unnormalized partials + (m,l) ---
  #pragma unroll
  for (int n = 0; n < 4; n++) {
    *(float2*)&Opart[((size_t)z*LQ + qb + g    )*CD + h*HD + n*8 + 2*t] =
        make_float2(oacc[n][0], oacc[n][1]);
    *(float2*)&Opart[((size_t)z*LQ + qb + g + 8)*CD + h*HD + n*8 + 2*t] =
        make_float2(oacc[n][2], oacc[n][3]);
  }
  if (t == 0) {
    ml[(z*LQ + qb + g    )*NHD + h] = make_float2(m_i[0], l_i[0]);
    ml[(z*LQ + qb + g + 8)*NHD + h] = make_float2(m_i[1], l_i[1]);
  }
  #undef KS_HI
  #undef KS_LO
  #undef PS
}

// merge the kv-splits; emits hi/lo (output feeds only GEMM A)
__global__ __launch_bounds__(256) void attn_merge(
    const float* __restrict__ Opart, const float2* __restrict__ ml,
    float* __restrict__ Ohi, float* __restrict__ Olo, int ostride, int ooff) {
  int row = blockIdx.x, c = threadIdx.x;
  int h = c >> 5;
  float2 mlp[NSPLIT];
  float m = -1e30f;
  #pragma unroll
  for (int p = 0; p < NSPLIT; p++) {
    mlp[p] = ml[(p*LQ + row)*NHD + h];
    m = fmaxf(m, mlp[p].x);
  }
  float l = 0.f, o = 0.f;
  #pragma unroll
  for (int p = 0; p < NSPLIT; p++) {
    float e = __expf(mlp[p].x - m);
    l += mlp[p].y * e;
    o += Opart[((size_t)p*LQ + row)*CD + c] * e;
  }
  float v = o / l;
  float hi = __uint_as_float(tf32r(v));
  Ohi[(size_t)row*ostride + ooff + c] = hi;
  Olo[(size_t)row*ostride + ooff + c] = __uint_as_float(tf32r(v - hi));
}

// ---------------- curr_Q / global_K / global_V construction ----------------
// emits fp32 q/gK/gV (attn Q + local attn) and gK/gV hi/lo (attn K/V)
__global__ __launch_bounds__(256) void make_kv_kernel(
    const float* __restrict__ qv, const float* __restrict__ idkv,
    float* __restrict__ q, float* __restrict__ gK, float* __restrict__ gV,
    float* __restrict__ khi, float* __restrict__ klo,
    float* __restrict__ vhi, float* __restrict__ vlo) {
  int l = blockIdx.x, c = threadIdx.x;
  float cq  = qv[(size_t)l*512 + c];
  float cv  = qv[(size_t)l*512 + 256 + c];
  float idk = idkv[(size_t)l*264 + (c >> 5)];
  float idv = idkv[(size_t)l*264 + 8 + c];
  float gk = cq * (1.f + tanhf(idk));
  float gv = cv + idv;
  size_t ofs = (size_t)l*CD + c;
  q[ofs] = cq;
  gK[ofs] = gk;
  gV[ofs] = gv;
  float kh = __uint_as_float(tf32r(gk));
  khi[ofs] = kh;
  klo[ofs] = __uint_as_float(tf32r(gk - kh));
  float vh = __uint_as_float(tf32r(gv));
  vhi[ofs] = vh;
  vlo[ofs] = __uint_as_float(tf32r(gv - vh));
}

// ---------------- Local 15x15 window attention (emits hi/lo) ----------------
__global__ __launch_bounds__(256) void local_attn_kernel(
    const float* __restrict__ Q, const float* __restrict__ Kp,
    const float* __restrict__ Vp,
    float* __restrict__ Ohi, float* __restrict__ Olo, int ostride, int ooff) {
  __shared__ float p_sh[8][232];
  int n = blockIdx.x;
  int r = n / GW, c = n % GW;
  int h = threadIdx.x >> 5, lane = threadIdx.x & 31;

  const float* qp = Q + (size_t)n*CD + h*HD;
  float4 qreg[8];
  #pragma unroll
  for (int i = 0; i < 8; i++) {
    qreg[i] = *(const float4*)(qp + i*4);
    qreg[i].x *= QSCALE; qreg[i].y *= QSCALE; qreg[i].z *= QSCALE; qreg[i].w *= QSCALE;
  }
  int i0 = max(7 - r, 0), i1 = min(GH + 7 - r, 15);
  int j0 = max(7 - c, 0), j1 = min(GW + 7 - c, 15);

  for (int w = lane; w < 225; w += 32) {
    int wi = w / 15, wj = w - wi*15;
    float logit = -1e30f;
    if (wi >= i0 && wi < i1 && wj >= j0 && wj < j1) {
      const float* kp = Kp + (size_t)((r+wi-7)*GW + (c+wj-7))*CD + h*HD;
      float acc = 0.f;
      #pragma unroll
      for (int i4 = 0; i4 < 8; i4++) {
        float4 kv = *(const float4*)(kp + i4*4);
        acc = fmaf(qreg[i4].x, kv.x, acc);
        acc = fmaf(qreg[i4].y, kv.y, acc);
        acc = fmaf(qreg[i4].z, kv.z, acc);
        acc = fmaf(qreg[i4].w, kv.w, acc);
      }
      logit = acc;
    }
    p_sh[h][w] = logit;
  }
  __syncwarp();
  float m = -1e30f;
  for (int ww = lane; ww < 225; ww += 32) m = fmaxf(m, p_sh[h][ww]);
  #pragma unroll
  for (int o = 16; o; o >>= 1) m = fmaxf(m, __shfl_xor_sync(0xffffffffu, m, o));
  float ssum = 0.f;
  for (int ww = lane; ww < 225; ww += 32) {
    float p = __expf(p_sh[h][ww] - m);
    p_sh[h][ww] = p;
    ssum += p;
  }
  #pragma unroll
  for (int o = 16; o; o >>= 1) ssum += __shfl_xor_sync(0xffffffffu, ssum, o);
  float inv = 1.f / ssum;
  __syncwarp();
  float oacc = 0.f;
  for (int wi = i0; wi < i1; wi++) {
    const float* vrow = Vp + (size_t)((r+wi-7)*GW + (c+j0-7))*CD + h*HD + lane;
    #pragma unroll 3
    for (int wj = j0; wj < j1; wj++, vrow += CD)
      oacc = fmaf(p_sh[h][wi*15+wj], *vrow, oacc);
  }
  float v = oacc * inv;
  float hi = __uint_as_float(tf32r(v));
  Ohi[(size_t)n*ostride + ooff + h*HD + lane] = hi;
  Olo[(size_t)n*ostride + ooff + h*HD + lane] = __uint_as_float(tf32r(v - hi));
}

// ---------------- GroupNorm stats ----------------
__global__ __launch_bounds__(1024) void gn_stats_kernel(
    const float* __restrict__ x, float* __restrict__ stats) {
  int g = blockIdx.x;
  float s = 0.f, s2 = 0.f;
  for (int idx = threadIdx.x; idx < LQ*32; idx += 1024) {
    int l = idx >> 5, ch = idx & 31;
    float v = x[(size_t)l*DFF + g*32 + ch];
    s += v; s2 += v*v;
  }
  #pragma unroll
  for (int o = 16; o; o >>= 1) {
    s  += __shfl_xor_sync(0xffffffffu, s,  o);
    s2 += __shfl_xor_sync(0xffffffffu, s2, o);
  }
  __shared__ float sh[32], sh2[32];
  int w = threadIdx.x >> 5, lane = threadIdx.x & 31;
  if (lane == 0) { sh[w] = s; sh2[w] = s2; }
  __syncthreads();
  if (w == 0) {
    s = sh[lane]; s2 = sh2[lane];
    #pragma unroll
    for (int o = 16; o; o >>= 1) {
      s  += __shfl_xor_sync(0xffffffffu, s,  o);
      s2 += __shfl_xor_sync(0xffffffffu, s2, o);
    }
    if (lane == 0) {
      const float invn = 1.f / (LQ * 32.f);
      float mean = s * invn;
      float var  = s2 * invn - mean*mean;
      stats[g*2]   = mean;
      stats[g*2+1] = rsqrtf(var + EPSV);
    }
  }
}

// ---------------- GN apply + exact GELU ----------------
__global__ __launch_bounds__(256) void gn_gelu_kernel(
    const float* __restrict__ x, const float* __restrict__ gg, const float* __restrict__ gb,
    const float* __restrict__ stats, float* __restrict__ y) {
  int idx = blockIdx.x * 256 + threadIdx.x;
  int ch = idx & (DFF-1);
  int g = ch >> 5;
  float v = (x[idx] - stats[g*2]) * stats[g*2+1] * gg[ch] + gb[ch];
  y[idx] = 0.5f * v * (1.f + erff(v * 0.70710678118654752f));
}

// ---------------- 5x5 depthwise conv, pad 2 (emits hi/lo) ----------------
__global__ __launch_bounds__(256) void dwconv_kernel(
    const float* __restrict__ x, const float* __restrict__ kern,
    float* __restrict__ yhi, float* __restrict__ ylo) {
  __shared__ float tile[12][12][32];
  __shared__ float kw[32][25];
  int tid = threadIdx.x;
  int ch0 = blockIdx.z * 32;
  int r0 = blockIdx.y * 8 - 2, c0 = blockIdx.x * 8 - 2;
  for (int e = tid; e < 12*12*32; e += 256) {
    int ch = e & 31;
    int sp = e >> 5;
    int ri = sp / 12, ci = sp % 12;
    int rr = r0 + ri, cc = c0 + ci;
    float v = 0.f;
    if ((unsigned)rr < (unsigned)GH && (unsigned)cc < (unsigned)GW)
      v = x[(size_t)(rr*GW + cc)*DFF + ch0 + ch];
    tile[ri][ci][ch] = v;
  }
  for (int e = tid; e < 32*25; e += 256)
    kw[e/25][e%25] = kern[(size_t)(ch0 + e/25)*25 + e%25];
  __syncthreads();
  for (int e = tid; e < 8*8*32; e += 256) {
    int ch = e & 31;
    int sp = e >> 5;
    int ri = sp >> 3, ci = sp & 7;
    float acc = 0.f;
    #pragma unroll
    for (int i = 0; i < 5; i++)
      #pragma unroll
      for (int j = 0; j < 5; j++)
        acc = fmaf(tile[ri+i][ci+j][ch], kw[ch][i*5+j], acc);
    int rr = blockIdx.y*8 + ri, cc = blockIdx.x*8 + ci;
    size_t ofs = (size_t)(rr*GW + cc)*DFF + ch0 + ch;
    float hi = __uint_as_float(tf32r(acc));
    yhi[ofs] = hi;
    ylo[ofs] = __uint_as_float(tf32r(acc - hi));
  }
}

// ---------------- launcher ----------------
extern "C" void kernel_launch(void* const* d_in, const int* in_sizes, int n_in,
                              void* d_out, int out_size) {
  const float* in_tgt   = (const float*)d_in[0];
  const float* id_emb   = (const float*)d_in[1];
  const float* self_pos = (const float*)d_in[2];
  const float* ln1_g = (const float*)d_in[3];
  const float* ln1_b = (const float*)d_in[4];
  const float* sa_wq = (const float*)d_in[5];
  const float* sa_bq = (const float*)d_in[6];
  const float* sa_wk = (const float*)d_in[7];
  const float* sa_bk = (const float*)d_in[8];
  const float* sa_wv = (const float*)d_in[9];
  const float* sa_bv = (const float*)d_in[10];
  const float* sa_wo = (const float*)d_in[11];
  const float* sa_bo = (const float*)d_in[12];
  const float* ln2_g = (const float*)d_in[13];
  const float* ln2_b = (const float*)d_in[14];
  const float* w_qv = (const float*)d_in[15];
  const float* b_qv = (const float*)d_in[16];
  const float* w_id = (const float*)d_in[17];
  const float* b_id = (const float*)d_in[18];
  const float* lt_wo = (const float*)d_in[19];
  const float* lt_bo = (const float*)d_in[20];
  const float* st_wo = (const float*)d_in[21];
  const float* st_bo = (const float*)d_in[22];
  const float* ln3_g = (const float*)d_in[23];
  const float* ln3_b = (const float*)d_in[24];
  const float* w1 = (const float*)d_in[25];
  const float* b1 = (const float*)d_in[26];
  const float* gn_g = (const float*)d_in[27];
  const float* gn_b = (const float*)d_in[28];
  const float* dw_k = (const float*)d_in[29];
  const float* w2 = (const float*)d_in[30];
  const float* b2 = (const float*)d_in[31];
  float* out = (float*)d_out;

  float *thi,*tlo,*qkhi,*qklo,*q,*khi,*klo,*vhi,*vlo,*tgtb,*qv,*idkv,*gK,*gV;
  float *acathi,*acatlo,*x,*x2,*xhi,*xlo,*stats,*bcat,*whi,*wlo,*idehi,*idelo,*opart;
  float2 *ml;
  cudaGetSymbolAddress((void**)&thi,    g_thi);
  cudaGetSymbolAddress((void**)&tlo,    g_tlo);
  cudaGetSymbolAddress((void**)&qkhi,   g_qkhi);
  cudaGetSymbolAddress((void**)&qklo,   g_qklo);
  cudaGetSymbolAddress((void**)&q,      g_q);
  cudaGetSymbolAddress((void**)&khi,    g_khi);
  cudaGetSymbolAddress((void**)&klo,    g_klo);
  cudaGetSymbolAddress((void**)&vhi,    g_vhi);
  cudaGetSymbolAddress((void**)&vlo,    g_vlo);
  cudaGetSymbolAddress((void**)&tgtb,   g_tgt);
  cudaGetSymbolAddress((void**)&qv,     g_qv);
  cudaGetSymbolAddress((void**)&idkv,   g_idkv);
  cudaGetSymbolAddress((void**)&gK,     g_gK);
  cudaGetSymbolAddress((void**)&gV,     g_gV);
  cudaGetSymbolAddress((void**)&acathi, g_acathi);
  cudaGetSymbolAddress((void**)&acatlo, g_acatlo);
  cudaGetSymbolAddress((void**)&x,      g_x);
  cudaGetSymbolAddress((void**)&x2,     g_x2);
  cudaGetSymbolAddress((void**)&xhi,    g_xhi);
  cudaGetSymbolAddress((void**)&xlo,    g_xlo);
  cudaGetSymbolAddress((void**)&stats,  g_stats);
  cudaGetSymbolAddress((void**)&bcat,   g_bcat);
  cudaGetSymbolAddress((void**)&whi,    g_whi);
  cudaGetSymbolAddress((void**)&wlo,    g_wlo);
  cudaGetSymbolAddress((void**)&idehi,  g_idehi);
  cudaGetSymbolAddress((void**)&idelo,  g_idelo);
  cudaGetSymbolAddress((void**)&opart,  g_opart);
  cudaGetSymbolAddress((void**)&ml,     g_ml);

  dim3 g66(4, 25);
  dim3 gQKV(4, 25, 3);
  dim3 gAttn(25, 8, NSPLIT);

  wsplit_all<<<(SPLIT_TOT+255)/256,256>>>(sa_wq, sa_wk, sa_wv, sa_wo, w_qv, w_id,
                                          lt_wo, st_wo, w1, w2, id_emb,
                                          whi, wlo, idehi, idelo);
  pack_b<<<1,256>>>(lt_bo, st_bo, bcat);
  cudaMemcpyAsync(tgtb, in_tgt, sizeof(float)*LQ*CD, cudaMemcpyDeviceToDevice, 0);

  // --- self attention ---
  ln_kernel<<<LQ,256>>>(in_tgt, ln1_g, ln1_b, thi, tlo, self_pos, qkhi, qklo);
  gemm_qkv<<<gQKV,256>>>(qkhi, qklo, thi, tlo, whi, wlo,
                         sa_bq, sa_bk, sa_bv, q, khi, klo, vhi, vlo);
  attn_kernel<<<gAttn,128>>>(q, khi, klo, vhi, vlo, opart, ml);
  attn_merge<<<LQ,256>>>(opart, ml, acathi, acatlo, 256, 0);
  gemm_nt<<<g66,256>>>(acathi, acatlo, whi+OFF_WO, wlo+OFF_WO, sa_bo, tgtb,
                       tgtb, nullptr, nullptr, LQ, CD, CD);

  // --- long/short term attention ---
  ln_kernel<<<LQ,256>>>(tgtb, ln2_g, ln2_b, thi, tlo, nullptr, nullptr, nullptr);
  gemm_nt<<<dim3(8,25),256>>>(thi, tlo, whi+OFF_WQV, wlo+OFF_WQV, b_qv, nullptr,
                              qv, nullptr, nullptr, LQ, 512, CD);
  gemm_nt<<<dim3(5,25),256>>>(idehi, idelo, whi+OFF_WID, wlo+OFF_WID, b_id, nullptr,
                              idkv, nullptr, nullptr, LQ, 264, CD);
  make_kv_kernel<<<LQ,256>>>(qv, idkv, q, gK, gV, khi, klo, vhi, vlo);
  attn_kernel<<<gAttn,128>>>(q, khi, klo, vhi, vlo, opart, ml);
  attn_merge<<<LQ,256>>>(opart, ml, acathi, acatlo, 512, 0);
  local_attn_kernel<<<LQ,256>>>(q, gK, gV, acathi, acatlo, 512, 256);
  gemm_nt<<<g66,256>>>(acathi, acatlo, whi+OFF_WCAT, wlo+OFF_WCAT, bcat, tgtb,
                       tgtb, nullptr, nullptr, LQ, CD, 512);

  // --- MLP: LN -> w1 -> GN -> GELU -> dwconv -> w2 ---
  ln_kernel<<<LQ,256>>>(tgtb, ln3_g, ln3_b, thi, tlo, nullptr, nullptr, nullptr);
  gemm_nt<<<dim3(16,25),256>>>(thi, tlo, whi+OFF_W1, wlo+OFF_W1, b1, nullptr,
                               x, nullptr, nullptr, LQ, DFF, CD);
  gn_stats_kernel<<<32,1024>>>(x, stats);
  gn_gelu_kernel<<<(LQ*DFF)/256,256>>>(x, gn_g, gn_b, stats, x2);
  dwconv_kernel<<<dim3(5,5,32),256>>>(x2, dw_k, xhi, xlo);
  gemm_nt<<<g66,256>>>(xhi, xlo, whi+OFF_W2, wlo+OFF_W2, b2, tgtb,
                       out, nullptr, nullptr, LQ, CD, DFF);
}